// round 9
// baseline (speedup 1.0000x reference)
#include <cuda_runtime.h>
#include <cuda_bf16.h>

// FuzzyLayer: out[b,s,d*I+i] = exp(-(x[b,s,i]-mu[d,i])^2 / sigma[d,i])
// B=16, S=2048, I=256, D=8.  256 MB write + 32 MB read -> HBM-write-bound.
//
// R8 -> R9: ROWS=16 (46.3) lost to R4's ROWS=32 (45.5) -> revert to ROWS=32.
// Single change vs R4: the x fill is now ONE cp.async commit group instead
// of LDG->reg->STS. Data drains global->SMEM directly, so the barrier
// releases one DRAM latency after issue (no register round-trip on the
// critical path), and 16 payload registers are freed.
// Kept: ONE barrier total, short blocks (grid 1024 -> cross-CTA desync),
// thread owns fixed output column group (poly coeffs in regs:
// exp2((a*x+b)*x+e)), all 8 'd' groups co-resident, float4 traffic,
// __stcs streaming stores, __launch_bounds__(512,4).

static constexpr int BS   = 16 * 2048;     // 32768 rows
static constexpr int ROWS = 32;            // rows per block (32 KB smem)

__device__ __forceinline__ float ex2_approx(float t) {
    float r;
    asm("ex2.approx.ftz.f32 %0, %1;" : "=f"(r) : "f"(t));
    return r;
}

__global__ void __launch_bounds__(512, 4)
fuzzy_kernel(const float4* __restrict__ x4,
             const float4* __restrict__ fp4,
             float4* __restrict__ out4)
{
    __shared__ float4 sx[ROWS * 64];         // 32 KB: ROWS rows of x (256 f32)

    const int tid = threadIdx.x;
    const int i4  = tid & 63;                // float4 group within I
    const int d   = tid >> 6;                // fuzzy degree

    const int bs0 = blockIdx.x * ROWS;

    // Fill: ROWS*64 = 2048 float4 over 512 threads = 4 cp.async of 16 B each,
    // one commit group. No register round-trip; frees the LSU early.
    {
        const float4* __restrict__ src = x4 + (size_t)bs0 * 64 + tid;
        unsigned sbase = (unsigned)__cvta_generic_to_shared(&sx[tid]);
#pragma unroll
        for (int k = 0; k < 4; ++k) {
            asm volatile("cp.async.cg.shared.global [%0], [%1], 16;"
                         :: "r"(sbase + k * 512 * 16), "l"(src + k * 512));
        }
        asm volatile("cp.async.commit_group;");
    }

    // Param load + coefficient setup overlaps the async fill.
    // fuzzy_params (2048,2) row-major: fp[2j]=mu_j, fp[2j+1]=sigma_j, j=d*256+i.
    const float4 p0 = fp4[d * 128 + i4 * 2];
    const float4 p1 = fp4[d * 128 + i4 * 2 + 1];

    const float L2E = 1.4426950408889634f;
    // exponent(x) = rs*(x-mu)^2 = (a*x + b)*x + e
    const float a0 = -L2E / p0.y, b0 = -2.f * a0 * p0.x, e0 = a0 * p0.x * p0.x;
    const float a1 = -L2E / p0.w, b1 = -2.f * a1 * p0.z, e1 = a1 * p0.z * p0.z;
    const float a2 = -L2E / p1.y, b2 = -2.f * a2 * p1.x, e2 = a2 * p1.x * p1.x;
    const float a3 = -L2E / p1.w, b3 = -2.f * a3 * p1.z, e3 = a3 * p1.z * p1.z;

    asm volatile("cp.async.wait_group 0;" ::: "memory");
    __syncthreads();

    float4* __restrict__ oout = out4 + (size_t)bs0 * 512 + tid;

#pragma unroll 4
    for (int r = 0; r < ROWS; ++r) {
        const float4 xv = sx[r * 64 + i4];

        float4 o;
        o.x = ex2_approx(fmaf(fmaf(a0, xv.x, b0), xv.x, e0));
        o.y = ex2_approx(fmaf(fmaf(a1, xv.y, b1), xv.y, e1));
        o.z = ex2_approx(fmaf(fmaf(a2, xv.z, b2), xv.z, e2));
        o.w = ex2_approx(fmaf(fmaf(a3, xv.w, b3), xv.w, e3));

        __stcs(oout + r * 512, o);
    }
}

extern "C" void kernel_launch(void* const* d_in, const int* in_sizes, int n_in,
                              void* d_out, int out_size)
{
    const float4* x4  = (const float4*)d_in[0];   // x: (16,2048,256) f32
    const float4* fp4 = (const float4*)d_in[1];   // fuzzy_params: (2048,2) f32
    float4* out4      = (float4*)d_out;           // (16,2048,2048) f32

    fuzzy_kernel<<<BS / ROWS, 512>>>(x4, fp4, out4);   // 1024 blocks
}